// round 1
// baseline (speedup 1.0000x reference)
#include <cuda_runtime.h>
#include <cuda_bf16.h>
#include <cstdint>

#define B_ 65536
#define D_ 512
#define K_ 1024
#define C_ 100

#define BM 128
#define BN 128
#define BK 8

// ---------------- scratch (device globals; no allocations allowed) ----------------
__device__ unsigned long long g_packed[B_];     // (dist_bits<<32)|k, atomicMin-merged
__device__ float g_xsq[B_];
__device__ float g_wsq[K_];
__device__ int   g_assign[B_];
__device__ int   g_counts[K_];
__device__ int   g_offsets[K_];
__device__ int   g_cursor[K_];
__device__ int   g_order[B_];
__device__ float g_es[(size_t)K_ * D_];         // embed_sum transposed [K][D]
__device__ int   g_bhist[K_ * C_];
__device__ float g_csnorm[K_];

// exact fp32 casts of the reference's python-double constants
__device__ __forceinline__ float GAM()  { return (float)0.99; }
__device__ __forceinline__ float OMG()  { return (float)(1.0 - 0.99); }        // 0.00999999977...
__device__ __forceinline__ float KEPS() { return (float)(1024 * 1e-5); }        // 0.01024

// ---------------- init scratch ----------------
__global__ void k_init() {
    int i = blockIdx.x * blockDim.x + threadIdx.x;
    if (i < B_)       g_packed[i] = ~0ull;
    if (i < K_)       g_counts[i] = 0;
    if (i < K_ * C_)  g_bhist[i]  = 0;
}

// ---------------- ||w_k||^2 ----------------
__global__ void k_wsq(const float* __restrict__ W) {
    int k = blockIdx.x * blockDim.x + threadIdx.x;   // 1024 threads
    float s0 = 0.f, s1 = 0.f, s2 = 0.f, s3 = 0.f;
    #pragma unroll 4
    for (int d = 0; d < D_; d += 4) {
        float v0 = W[(size_t)(d + 0) * K_ + k];
        float v1 = W[(size_t)(d + 1) * K_ + k];
        float v2 = W[(size_t)(d + 2) * K_ + k];
        float v3 = W[(size_t)(d + 3) * K_ + k];
        s0 += v0 * v0; s1 += v1 * v1; s2 += v2 * v2; s3 += v3 * v3;
    }
    g_wsq[k] = (s0 + s1) + (s2 + s3);
}

// ---------------- ||x_b||^2 (one warp per row) ----------------
__global__ void k_xsq(const float* __restrict__ X) {
    int warp = (blockIdx.x * blockDim.x + threadIdx.x) >> 5;
    int lane = threadIdx.x & 31;
    if (warp >= B_) return;
    const float4* p = (const float4*)(X + (size_t)warp * D_);
    float s = 0.f;
    #pragma unroll
    for (int j = lane; j < D_ / 4; j += 32) {
        float4 v = p[j];
        s += v.x * v.x + v.y * v.y + v.z * v.z + v.w * v.w;
    }
    #pragma unroll
    for (int o = 16; o; o >>= 1) s += __shfl_xor_sync(0xFFFFFFFFu, s, o);
    if (lane == 0) g_xsq[warp] = s;
}

// ---------------- fused fp32 GEMM + row argmin (f32x2 FFMA2 path) ----------------
__global__ void __launch_bounds__(256, 2)
k_gemm_argmin(const float* __restrict__ X, const float* __restrict__ W) {
    __shared__ float XsDup[2][BK][2 * BM];   // duplicated pairs: row r at words [2r,2r+1]
    __shared__ float Ws[2][BK][BN];
    __shared__ float wsq_s[BN];
    __shared__ float xsq_s[BM];
    __shared__ unsigned long long rowmin[BM];

    const int tid    = threadIdx.x;
    const int bm     = blockIdx.x;          // 512 row blocks
    const int bn     = blockIdx.y;          // 8 col blocks
    const int warpId = tid >> 5;
    const int lane   = tid & 31;
    const int tr = (warpId & 3) * 32 + (lane >> 3) * 8;   // thread row base (8 rows)
    const int tc = (warpId >> 2) * 64 + (lane & 7) * 8;   // thread col base (8 cols)

    const int xRow = tid >> 1;
    const int xCol = (tid & 1) * 4;
    const float* Xg = X + (size_t)(bm * BM + xRow) * D_ + xCol;
    const int wRow = tid >> 5;               // 0..7
    const int wCol = (tid & 31) * 4;
    const float* Wg = W + (size_t)wRow * K_ + bn * BN + wCol;

    if (tid < BM) {
        rowmin[tid] = ~0ull;
        xsq_s[tid]  = g_xsq[bm * BM + tid];
        wsq_s[tid]  = g_wsq[bn * BN + tid];
    }

    // prologue: stage 0
    {
        float4 xv = *(const float4*)Xg;
        float4 wv = *(const float4*)Wg;
        *(float2*)&XsDup[0][xCol + 0][2 * xRow] = make_float2(xv.x, xv.x);
        *(float2*)&XsDup[0][xCol + 1][2 * xRow] = make_float2(xv.y, xv.y);
        *(float2*)&XsDup[0][xCol + 2][2 * xRow] = make_float2(xv.z, xv.z);
        *(float2*)&XsDup[0][xCol + 3][2 * xRow] = make_float2(xv.w, xv.w);
        *(float4*)&Ws[0][wRow][wCol] = wv;
    }
    __syncthreads();

    unsigned long long acc[8][4];
    #pragma unroll
    for (int i = 0; i < 8; ++i)
        #pragma unroll
        for (int j = 0; j < 4; ++j) acc[i][j] = 0ull;

    int s = 0;
    for (int kt = 0; kt < D_ / BK; ++kt) {
        float4 xv, wv;
        const bool pf = (kt + 1 < D_ / BK);
        if (pf) {
            xv = *(const float4*)(Xg + (kt + 1) * BK);
            wv = *(const float4*)(Wg + (size_t)(kt + 1) * BK * K_);
        }
        #pragma unroll
        for (int kk = 0; kk < BK; ++kk) {
            union U { uint4 v; unsigned long long u[2]; };
            U A0, A1, A2, A3, B0, B1;
            A0.v = *(const uint4*)&XsDup[s][kk][2 * tr + 0];
            A1.v = *(const uint4*)&XsDup[s][kk][2 * tr + 4];
            A2.v = *(const uint4*)&XsDup[s][kk][2 * tr + 8];
            A3.v = *(const uint4*)&XsDup[s][kk][2 * tr + 12];
            B0.v = *(const uint4*)&Ws[s][kk][tc + 0];
            B1.v = *(const uint4*)&Ws[s][kk][tc + 4];
            unsigned long long a[8] = {A0.u[0], A0.u[1], A1.u[0], A1.u[1],
                                       A2.u[0], A2.u[1], A3.u[0], A3.u[1]};
            unsigned long long b[4] = {B0.u[0], B0.u[1], B1.u[0], B1.u[1]};
            #pragma unroll
            for (int i = 0; i < 8; ++i)
                #pragma unroll
                for (int j = 0; j < 4; ++j)
                    asm("fma.rn.f32x2 %0, %1, %2, %0;"
                        : "+l"(acc[i][j]) : "l"(a[i]), "l"(b[j]));
        }
        if (pf) {
            int ns = s ^ 1;
            *(float2*)&XsDup[ns][xCol + 0][2 * xRow] = make_float2(xv.x, xv.x);
            *(float2*)&XsDup[ns][xCol + 1][2 * xRow] = make_float2(xv.y, xv.y);
            *(float2*)&XsDup[ns][xCol + 2][2 * xRow] = make_float2(xv.z, xv.z);
            *(float2*)&XsDup[ns][xCol + 3][2 * xRow] = make_float2(xv.w, xv.w);
            *(float4*)&Ws[ns][wRow][wCol] = wv;
        }
        __syncthreads();
        s ^= 1;
    }

    // epilogue: dist = sqrt(max((xsq - 2*dot) + wsq, 0)); argmin with lowest-k tie-break
    #pragma unroll
    for (int i = 0; i < 8; ++i) {
        float xs = xsq_s[tr + i];
        unsigned long long best = ~0ull;
        #pragma unroll
        for (int j = 0; j < 4; ++j) {
            float lo = __uint_as_float((unsigned)(acc[i][j] & 0xFFFFFFFFull));
            float hi = __uint_as_float((unsigned)(acc[i][j] >> 32));
            int c0 = bn * BN + tc + 2 * j;
            float d0 = (xs - 2.0f * lo) + wsq_s[tc + 2 * j];
            float d1 = (xs - 2.0f * hi) + wsq_s[tc + 2 * j + 1];
            d0 = __fsqrt_rn(fmaxf(d0, 0.0f));
            d1 = __fsqrt_rn(fmaxf(d1, 0.0f));
            unsigned long long p0 = ((unsigned long long)__float_as_uint(d0) << 32) | (unsigned)c0;
            unsigned long long p1 = ((unsigned long long)__float_as_uint(d1) << 32) | (unsigned)(c0 + 1);
            best = min(best, min(p0, p1));
        }
        atomicMin(&rowmin[tr + i], best);
    }
    __syncthreads();
    if (tid < BM) atomicMin(&g_packed[bm * BM + tid], rowmin[tid]);
}

// ---------------- unpack argmin, counts, class histogram ----------------
__global__ void k_post(const int* __restrict__ keys, float* __restrict__ out_am) {
    int b = blockIdx.x * blockDim.x + threadIdx.x;
    if (b >= B_) return;
    int k = (int)(g_packed[b] & 0xFFFFFFFFull);
    g_assign[b] = k;
    out_am[b] = (float)k;
    atomicAdd(&g_counts[k], 1);
    atomicAdd(&g_bhist[k * C_ + keys[b]], 1);
}

// ---------------- cluster-size EMA, normalization, prefix scan ----------------
__global__ void k_stats(const float* __restrict__ cluster_size, float* __restrict__ out_ncs) {
    __shared__ float red[K_];
    __shared__ int   scan[K_];
    int t = threadIdx.x;
    int cnt = g_counts[t];
    float nidx = (cnt == 0) ? 1.0f : (float)cnt;
    float ncs = cluster_size[t] * GAM() + OMG() * nidx;
    out_ncs[t] = ncs;

    red[t] = ncs; __syncthreads();
    #pragma unroll
    for (int o = 512; o; o >>= 1) {
        if (t < o) red[t] += red[t + o];
        __syncthreads();
    }
    float n = red[0];
    g_csnorm[t] = ((ncs + 1e-5f) / (n + KEPS())) * n;

    scan[t] = cnt; __syncthreads();
    for (int o = 1; o < K_; o <<= 1) {
        int v = (t >= o) ? scan[t - o] : 0;
        __syncthreads();
        scan[t] += v;
        __syncthreads();
    }
    int excl = scan[t] - cnt;
    g_offsets[t] = excl;
    g_cursor[t]  = excl;
}

// ---------------- counting-sort scatter ----------------
__global__ void k_scatter() {
    int b = blockIdx.x * blockDim.x + threadIdx.x;
    if (b >= B_) return;
    int k = g_assign[b];
    int pos = atomicAdd(&g_cursor[k], 1);
    g_order[pos] = b;
}

// ---------------- per-cluster embed_sum (coalesced gather) ----------------
__global__ void k_embed(const float* __restrict__ X) {
    int k = blockIdx.x;
    int d = threadIdx.x;                 // 512 threads == D
    int start = g_offsets[k], cnt = g_counts[k];
    float acc = 0.f;
    for (int i = 0; i < cnt; ++i) {
        int b = g_order[start + i];
        acc += X[(size_t)b * D_ + d];
    }
    g_es[(size_t)k * D_ + d] = acc;
}

// ---------------- embed_avg EMA + weight, transposed tiles for coalescing ----------------
__global__ void k_ema(const float* __restrict__ ea,
                      float* __restrict__ out_w, float* __restrict__ out_nea) {
    __shared__ float tile[32][33];
    int d0 = blockIdx.x * 32, k0 = blockIdx.y * 32;
    int tx = threadIdx.x, ty = threadIdx.y;
    tile[ty][tx] = g_es[(size_t)(k0 + ty) * D_ + d0 + tx];   // coalesced along d
    __syncthreads();
    int d = d0 + ty, k = k0 + tx;
    size_t idx = (size_t)d * K_ + k;                          // coalesced along k
    float nea = ea[idx] * GAM() + OMG() * tile[tx][ty];
    out_nea[idx] = nea;
    out_w[idx]   = nea / g_csnorm[k];
}

// ---------------- hist EMA ----------------
__global__ void k_hist(const float* __restrict__ hist, float* __restrict__ out_h) {
    int i = blockIdx.x * blockDim.x + threadIdx.x;
    if (i < K_ * C_) out_h[i] = hist[i] * GAM() + OMG() * (float)g_bhist[i];
}

// ---------------- launch ----------------
extern "C" void kernel_launch(void* const* d_in, const int* in_sizes, int n_in,
                              void* d_out, int out_size) {
    const float* X    = (const float*)d_in[0];   // [B,D]
    const int*   keys = (const int*)  d_in[1];   // [B]
    const float* W    = (const float*)d_in[2];   // [D,K]
    const float* cs   = (const float*)d_in[3];   // [K]
    const float* ea   = (const float*)d_in[4];   // [D,K]
    const float* hist = (const float*)d_in[5];   // [K,C]

    float* out      = (float*)d_out;
    float* out_w    = out;                            // 524288
    float* out_ncs  = out + 524288;                   // 1024
    float* out_nea  = out + 525312;                   // 524288
    float* out_hist = out + 1049600;                  // 102400
    float* out_am   = out + 1152000;                  // 65536

    k_init<<<(K_ * C_ + 255) / 256, 256>>>();
    k_wsq<<<K_ / 256, 256>>>(W);
    k_xsq<<<(B_ * 32) / 256, 256>>>(X);

    dim3 gg(B_ / BM, K_ / BN);
    k_gemm_argmin<<<gg, 256>>>(X, W);

    k_post<<<B_ / 256, 256>>>(keys, out_am);
    k_stats<<<1, K_>>>(cs, out_ncs);
    k_scatter<<<B_ / 256, 256>>>();
    k_embed<<<K_, D_>>>(X);

    dim3 ge(D_ / 32, K_ / 32);
    k_ema<<<ge, dim3(32, 32)>>>(ea, out_w, out_nea);
    k_hist<<<(K_ * C_ + 255) / 256, 256>>>(hist, out_hist);
}

// round 2
// speedup vs baseline: 1.1629x; 1.1629x over previous
#include <cuda_runtime.h>
#include <cuda_bf16.h>
#include <cstdint>

#define B_ 65536
#define D_ 512
#define K_ 1024
#define C_ 100

#define BM 128
#define BN 128
#define BK 8

// ---------------- scratch (device globals; no allocations allowed) ----------------
__device__ unsigned long long g_packed[B_];     // (dist_bits<<32)|k, atomicMin-merged
__device__ float g_xsq[B_];
__device__ float g_wsq[K_];
__device__ int   g_assign[B_];
__device__ int   g_counts[K_];
__device__ int   g_offsets[K_];
__device__ int   g_cursor[K_];
__device__ int   g_order[B_];
__device__ float g_es[(size_t)K_ * D_];         // embed_sum transposed [K][D]
__device__ int   g_bhist[K_ * C_];
__device__ float g_csnorm[K_];

// exact fp32 casts of the reference's python-double constants
__device__ __forceinline__ float GAM()  { return (float)0.99; }
__device__ __forceinline__ float OMG()  { return (float)(1.0 - 0.99); }
__device__ __forceinline__ float KEPS() { return (float)(1024 * 1e-5); }

// ---------------- init scratch ----------------
__global__ void k_init() {
    int i = blockIdx.x * blockDim.x + threadIdx.x;
    if (i < B_)       g_packed[i] = ~0ull;
    if (i < K_)       g_counts[i] = 0;
    if (i < K_ * C_)  g_bhist[i]  = 0;
}

// ---------------- ||w_k||^2 ----------------
__global__ void k_wsq(const float* __restrict__ W) {
    int k = blockIdx.x * blockDim.x + threadIdx.x;   // 1024 threads
    float s0 = 0.f, s1 = 0.f, s2 = 0.f, s3 = 0.f;
    #pragma unroll 4
    for (int d = 0; d < D_; d += 4) {
        float v0 = W[(size_t)(d + 0) * K_ + k];
        float v1 = W[(size_t)(d + 1) * K_ + k];
        float v2 = W[(size_t)(d + 2) * K_ + k];
        float v3 = W[(size_t)(d + 3) * K_ + k];
        s0 += v0 * v0; s1 += v1 * v1; s2 += v2 * v2; s3 += v3 * v3;
    }
    g_wsq[k] = (s0 + s1) + (s2 + s3);
}

// ---------------- ||x_b||^2 (one warp per row) ----------------
__global__ void k_xsq(const float* __restrict__ X) {
    int warp = (blockIdx.x * blockDim.x + threadIdx.x) >> 5;
    int lane = threadIdx.x & 31;
    if (warp >= B_) return;
    const float4* p = (const float4*)(X + (size_t)warp * D_);
    float s = 0.f;
    #pragma unroll
    for (int j = lane; j < D_ / 4; j += 32) {
        float4 v = p[j];
        s += v.x * v.x + v.y * v.y + v.z * v.z + v.w * v.w;
    }
    #pragma unroll
    for (int o = 16; o; o >>= 1) s += __shfl_xor_sync(0xFFFFFFFFu, s, o);
    if (lane == 0) g_xsq[warp] = s;
}

// ---------------- fused fp32 GEMM + row argmin (f32x2, register-side dup) ----------------
__global__ void __launch_bounds__(256, 2)
k_gemm_argmin(const float* __restrict__ X, const float* __restrict__ W) {
    __shared__ float Xs[2][BK][BM];
    __shared__ float Ws[2][BK][BN];
    __shared__ float wsq_s[BN];
    __shared__ float xsq_s[BM];
    __shared__ unsigned long long rowmin[BM];

    const int tid    = threadIdx.x;
    const int bn     = blockIdx.x;           // 8 col blocks (fast: share X in L2)
    const int bm     = blockIdx.y;           // 512 row blocks
    const int warpId = tid >> 5;
    const int lane   = tid & 31;
    const int tr = (warpId & 3) * 32 + (lane >> 3) * 8;   // thread row base (8 rows)
    const int tc = (warpId >> 2) * 64 + (lane & 7) * 8;   // thread col base (8 cols)

    const int xRow = tid >> 1;
    const int xCol = (tid & 1) * 4;
    const float* Xg = X + (size_t)(bm * BM + xRow) * D_ + xCol;
    const int wRow = tid >> 5;               // 0..7
    const int wCol = (tid & 31) * 4;
    const float* Wg = W + (size_t)wRow * K_ + bn * BN + wCol;

    if (tid < BM) {
        rowmin[tid] = ~0ull;
        xsq_s[tid]  = g_xsq[bm * BM + tid];
        wsq_s[tid]  = g_wsq[bn * BN + tid];
    }

    // prologue: stage 0
    {
        float4 xv = *(const float4*)Xg;
        float4 wv = *(const float4*)Wg;
        Xs[0][xCol + 0][xRow] = xv.x;
        Xs[0][xCol + 1][xRow] = xv.y;
        Xs[0][xCol + 2][xRow] = xv.z;
        Xs[0][xCol + 3][xRow] = xv.w;
        *(float4*)&Ws[0][wRow][wCol] = wv;
    }
    __syncthreads();

    unsigned long long acc[8][4];
    #pragma unroll
    for (int i = 0; i < 8; ++i)
        #pragma unroll
        for (int j = 0; j < 4; ++j) acc[i][j] = 0ull;

    int s = 0;
    for (int kt = 0; kt < D_ / BK; ++kt) {
        float4 xv, wv;
        const bool pf = (kt + 1 < D_ / BK);
        if (pf) {
            xv = *(const float4*)(Xg + (kt + 1) * BK);
            wv = *(const float4*)(Wg + (size_t)(kt + 1) * BK * K_);
        }
        #pragma unroll
        for (int kk = 0; kk < BK; ++kk) {
            // A fragment: 8 floats (broadcast-heavy LDS), then dup to f32x2 pairs
            float4 A0 = *(const float4*)&Xs[s][kk][tr + 0];
            float4 A1 = *(const float4*)&Xs[s][kk][tr + 4];
            float af[8] = {A0.x, A0.y, A0.z, A0.w, A1.x, A1.y, A1.z, A1.w};
            unsigned long long a[8];
            #pragma unroll
            for (int i = 0; i < 8; ++i)
                asm("mov.b64 %0, {%1, %1};" : "=l"(a[i]) : "f"(af[i]));
            // B fragment: 8 floats as 4 native f32x2 pairs
            union U { uint4 v; unsigned long long u[2]; };
            U B0, B1;
            B0.v = *(const uint4*)&Ws[s][kk][tc + 0];
            B1.v = *(const uint4*)&Ws[s][kk][tc + 4];
            unsigned long long b[4] = {B0.u[0], B0.u[1], B1.u[0], B1.u[1]};
            #pragma unroll
            for (int i = 0; i < 8; ++i)
                #pragma unroll
                for (int j = 0; j < 4; ++j)
                    asm("fma.rn.f32x2 %0, %1, %2, %0;"
                        : "+l"(acc[i][j]) : "l"(a[i]), "l"(b[j]));
        }
        if (pf) {
            int ns = s ^ 1;
            Xs[ns][xCol + 0][xRow] = xv.x;
            Xs[ns][xCol + 1][xRow] = xv.y;
            Xs[ns][xCol + 2][xRow] = xv.z;
            Xs[ns][xCol + 3][xRow] = xv.w;
            *(float4*)&Ws[ns][wRow][wCol] = wv;
        }
        __syncthreads();
        s ^= 1;
    }

    // epilogue: dist = sqrt(max((xsq - 2*dot) + wsq, 0)); argmin, lowest-k ties
    #pragma unroll
    for (int i = 0; i < 8; ++i) {
        float xs = xsq_s[tr + i];
        unsigned long long best = ~0ull;
        #pragma unroll
        for (int j = 0; j < 4; ++j) {
            float lo = __uint_as_float((unsigned)(acc[i][j] & 0xFFFFFFFFull));
            float hi = __uint_as_float((unsigned)(acc[i][j] >> 32));
            int c0 = bn * BN + tc + 2 * j;
            float d0 = (xs - 2.0f * lo) + wsq_s[tc + 2 * j];
            float d1 = (xs - 2.0f * hi) + wsq_s[tc + 2 * j + 1];
            d0 = __fsqrt_rn(fmaxf(d0, 0.0f));
            d1 = __fsqrt_rn(fmaxf(d1, 0.0f));
            unsigned long long p0 = ((unsigned long long)__float_as_uint(d0) << 32) | (unsigned)c0;
            unsigned long long p1 = ((unsigned long long)__float_as_uint(d1) << 32) | (unsigned)(c0 + 1);
            best = min(best, min(p0, p1));
        }
        atomicMin(&rowmin[tr + i], best);
    }
    __syncthreads();
    if (tid < BM) atomicMin(&g_packed[bm * BM + tid], rowmin[tid]);
}

// ---------------- unpack argmin, counts, class histogram ----------------
__global__ void k_post(const int* __restrict__ keys, float* __restrict__ out_am) {
    int b = blockIdx.x * blockDim.x + threadIdx.x;
    if (b >= B_) return;
    int k = (int)(g_packed[b] & 0xFFFFFFFFull);
    g_assign[b] = k;
    out_am[b] = (float)k;
    atomicAdd(&g_counts[k], 1);
    atomicAdd(&g_bhist[k * C_ + keys[b]], 1);
}

// ---------------- cluster-size EMA, normalization, prefix scan ----------------
__global__ void k_stats(const float* __restrict__ cluster_size, float* __restrict__ out_ncs) {
    __shared__ float red[K_];
    __shared__ int   scan[K_];
    int t = threadIdx.x;
    int cnt = g_counts[t];
    float nidx = (cnt == 0) ? 1.0f : (float)cnt;
    float ncs = cluster_size[t] * GAM() + OMG() * nidx;
    out_ncs[t] = ncs;

    red[t] = ncs; __syncthreads();
    #pragma unroll
    for (int o = 512; o; o >>= 1) {
        if (t < o) red[t] += red[t + o];
        __syncthreads();
    }
    float n = red[0];
    g_csnorm[t] = ((ncs + 1e-5f) / (n + KEPS())) * n;

    scan[t] = cnt; __syncthreads();
    for (int o = 1; o < K_; o <<= 1) {
        int v = (t >= o) ? scan[t - o] : 0;
        __syncthreads();
        scan[t] += v;
        __syncthreads();
    }
    int excl = scan[t] - cnt;
    g_offsets[t] = excl;
    g_cursor[t]  = excl;
}

// ---------------- counting-sort scatter ----------------
__global__ void k_scatter() {
    int b = blockIdx.x * blockDim.x + threadIdx.x;
    if (b >= B_) return;
    int k = g_assign[b];
    int pos = atomicAdd(&g_cursor[k], 1);
    g_order[pos] = b;
}

// ---------------- per-cluster embed_sum (coalesced gather, MLP=4) ----------------
__global__ void k_embed(const float* __restrict__ X) {
    int k = blockIdx.x;
    int d = threadIdx.x;                 // 512 threads == D
    int start = g_offsets[k], cnt = g_counts[k];
    const int* ord = g_order + start;
    float a0 = 0.f, a1 = 0.f, a2 = 0.f, a3 = 0.f;
    int i = 0;
    for (; i + 4 <= cnt; i += 4) {
        int b0 = ord[i + 0], b1 = ord[i + 1], b2 = ord[i + 2], b3 = ord[i + 3];
        a0 += X[(size_t)b0 * D_ + d];
        a1 += X[(size_t)b1 * D_ + d];
        a2 += X[(size_t)b2 * D_ + d];
        a3 += X[(size_t)b3 * D_ + d];
    }
    for (; i < cnt; ++i) a0 += X[(size_t)ord[i] * D_ + d];
    g_es[(size_t)k * D_ + d] = (a0 + a1) + (a2 + a3);
}

// ---------------- embed_avg EMA + weight, transposed tiles for coalescing ----------------
__global__ void k_ema(const float* __restrict__ ea,
                      float* __restrict__ out_w, float* __restrict__ out_nea) {
    __shared__ float tile[32][33];
    int d0 = blockIdx.x * 32, k0 = blockIdx.y * 32;
    int tx = threadIdx.x, ty = threadIdx.y;
    tile[ty][tx] = g_es[(size_t)(k0 + ty) * D_ + d0 + tx];   // coalesced along d
    __syncthreads();
    int d = d0 + ty, k = k0 + tx;
    size_t idx = (size_t)d * K_ + k;                          // coalesced along k
    float nea = ea[idx] * GAM() + OMG() * tile[tx][ty];
    out_nea[idx] = nea;
    out_w[idx]   = nea / g_csnorm[k];
}

// ---------------- hist EMA ----------------
__global__ void k_hist(const float* __restrict__ hist, float* __restrict__ out_h) {
    int i = blockIdx.x * blockDim.x + threadIdx.x;
    if (i < K_ * C_) out_h[i] = hist[i] * GAM() + OMG() * (float)g_bhist[i];
}

// ---------------- launch ----------------
extern "C" void kernel_launch(void* const* d_in, const int* in_sizes, int n_in,
                              void* d_out, int out_size) {
    const float* X    = (const float*)d_in[0];   // [B,D]
    const int*   keys = (const int*)  d_in[1];   // [B]
    const float* W    = (const float*)d_in[2];   // [D,K]
    const float* cs   = (const float*)d_in[3];   // [K]
    const float* ea   = (const float*)d_in[4];   // [D,K]
    const float* hist = (const float*)d_in[5];   // [K,C]

    float* out      = (float*)d_out;
    float* out_w    = out;                            // 524288
    float* out_ncs  = out + 524288;                   // 1024
    float* out_nea  = out + 525312;                   // 524288
    float* out_hist = out + 1049600;                  // 102400
    float* out_am   = out + 1152000;                  // 65536

    k_init<<<(K_ * C_ + 255) / 256, 256>>>();
    k_wsq<<<K_ / 256, 256>>>(W);
    k_xsq<<<(B_ * 32) / 256, 256>>>(X);

    dim3 gg(K_ / BN, B_ / BM);     // bn fast -> X tiles shared in L2
    k_gemm_argmin<<<gg, 256>>>(X, W);

    k_post<<<B_ / 256, 256>>>(keys, out_am);
    k_stats<<<1, K_>>>(cs, out_ncs);
    k_scatter<<<B_ / 256, 256>>>();
    k_embed<<<K_, D_>>>(X);

    dim3 ge(D_ / 32, K_ / 32);
    k_ema<<<ge, dim3(32, 32)>>>(ea, out_w, out_nea);
    k_hist<<<(K_ * C_ + 255) / 256, 256>>>(hist, out_hist);
}

// round 5
// speedup vs baseline: 3.0027x; 2.5820x over previous
#include <cuda_runtime.h>
#include <cuda_bf16.h>
#include <cuda_fp16.h>
#include <cstdint>

#define B_ 65536
#define D_ 512
#define K_ 1024
#define C_ 100
#define TAU 3.5f

// ---------------- scratch (device globals; no allocations allowed) ----------------
__device__ __align__(16) __half          g_d2h[(size_t)B_ * K_];   // 128MB approx d2 (fp16)
__device__ __align__(16) __nv_bfloat16   g_Xb [(size_t)B_ * D_];   // 64MB  X bf16
__device__ __align__(16) __nv_bfloat16   g_Wt [(size_t)K_ * D_];   // 1MB   W^T bf16
__device__ __align__(16) float           g_Wtf[(size_t)K_ * D_];   // 2MB   W^T fp32
__device__ float g_xsq[B_];
__device__ float g_wsq[K_];
__device__ int   g_assign[B_];
__device__ int   g_counts[K_];
__device__ int   g_offsets[K_];
__device__ int   g_cursor[K_];
__device__ int   g_order[B_];
__device__ float g_es[(size_t)K_ * D_];
__device__ int   g_bhist[K_ * C_];
__device__ float g_csnorm[K_];

__device__ __forceinline__ float GAM()  { return (float)0.99; }
__device__ __forceinline__ float OMG()  { return (float)(1.0 - 0.99); }
__device__ __forceinline__ float KEPS() { return (float)(1024 * 1e-5); }

// ---------------- PTX helpers (sm_80-era ISA only; no tcgen05) ----------------
__device__ __forceinline__ uint32_t smem_u32(const void* p) {
    uint32_t a;
    asm("{ .reg .u64 t; cvta.to.shared.u64 t, %1; cvt.u32.u64 %0, t; }" : "=r"(a) : "l"(p));
    return a;
}
__device__ __forceinline__ void cp16(uint32_t s, const void* g) {
    asm volatile("cp.async.cg.shared.global [%0], [%1], 16;" :: "r"(s), "l"(g) : "memory");
}
#define CP_COMMIT() asm volatile("cp.async.commit_group;" ::: "memory")
#define CP_WAIT1()  asm volatile("cp.async.wait_group 1;" ::: "memory")
#define CP_WAIT0()  asm volatile("cp.async.wait_group 0;" ::: "memory")

__device__ __forceinline__ void ldm_x4(uint32_t& r0, uint32_t& r1, uint32_t& r2, uint32_t& r3, uint32_t a) {
    asm volatile("ldmatrix.sync.aligned.m8n8.x4.shared.b16 {%0,%1,%2,%3}, [%4];"
                 : "=r"(r0), "=r"(r1), "=r"(r2), "=r"(r3) : "r"(a));
}
__device__ __forceinline__ void mma16816(float* c, const uint32_t* a, const uint32_t* b) {
    asm volatile("mma.sync.aligned.m16n8k16.row.col.f32.bf16.bf16.f32 "
                 "{%0,%1,%2,%3}, {%4,%5,%6,%7}, {%8,%9}, {%0,%1,%2,%3};"
                 : "+f"(c[0]), "+f"(c[1]), "+f"(c[2]), "+f"(c[3])
                 : "r"(a[0]), "r"(a[1]), "r"(a[2]), "r"(a[3]), "r"(b[0]), "r"(b[1]));
}

// ---------------- init scratch ----------------
__global__ void k_init() {
    int i = blockIdx.x * blockDim.x + threadIdx.x;
    if (i < K_)       g_counts[i] = 0;
    if (i < K_ * C_)  g_bhist[i]  = 0;
}

// ---------------- X -> bf16 + ||x||^2 (warp per row) ----------------
__global__ void k_xconv(const float* __restrict__ X) {
    int w = (blockIdx.x * blockDim.x + threadIdx.x) >> 5;
    int lane = threadIdx.x & 31;
    if (w >= B_) return;
    const float4* p = (const float4*)(X + (size_t)w * D_);
    uint32_t* dst = (uint32_t*)(g_Xb + (size_t)w * D_);
    float s = 0.f;
    #pragma unroll
    for (int j = 0; j < 4; ++j) {
        float4 v = p[lane + j * 32];
        s += v.x * v.x + v.y * v.y + v.z * v.z + v.w * v.w;
        __nv_bfloat162 h0 = __floats2bfloat162_rn(v.x, v.y);
        __nv_bfloat162 h1 = __floats2bfloat162_rn(v.z, v.w);
        dst[(lane + j * 32) * 2 + 0] = *(uint32_t*)&h0;
        dst[(lane + j * 32) * 2 + 1] = *(uint32_t*)&h1;
    }
    #pragma unroll
    for (int o = 16; o; o >>= 1) s += __shfl_xor_sync(0xFFFFFFFFu, s, o);
    if (lane == 0) g_xsq[w] = s;
}

// ---------------- W transpose: bf16 + fp32 copies ----------------
__global__ void k_wt(const float* __restrict__ W) {
    __shared__ float tile[32][33];
    int d0 = blockIdx.x * 32, k0 = blockIdx.y * 32;
    int tx = threadIdx.x, ty = threadIdx.y;
    tile[ty][tx] = W[(size_t)(d0 + ty) * K_ + k0 + tx];
    __syncthreads();
    int k = k0 + ty, d = d0 + tx;
    float v = tile[tx][ty];
    g_Wtf[(size_t)k * D_ + d] = v;
    g_Wt[(size_t)k * D_ + d]  = __float2bfloat16_rn(v);
}

// ---------------- ||w_k||^2 (block per column, deterministic tree) ----------------
__global__ void k_wsq(const float* __restrict__ W) {
    __shared__ float red[128];
    int k = blockIdx.x, t = threadIdx.x;
    float s = 0.f;
    #pragma unroll
    for (int d = t; d < D_; d += 128) { float v = W[(size_t)d * K_ + k]; s += v * v; }
    red[t] = s; __syncthreads();
    #pragma unroll
    for (int o = 64; o; o >>= 1) { if (t < o) red[t] += red[t + o]; __syncthreads(); }
    if (t == 0) g_wsq[k] = red[0];
}

// ---------------- bf16 HMMA GEMM: d2h[b,k] = xsq - 2*x.w + wsq (fp16 out) ----------------
// Tile 128x128, BK=64, cp.async double buffer, smem pitch 144B (conflict-free ldmatrix)
#define PITCH 144
#define TBUF  18432   // 128 rows * 144 B

__global__ void __launch_bounds__(256, 2)
k_gemm_bf16() {
    extern __shared__ char dynsmem[];
    __shared__ float wsq_s[128];

    const int tid  = threadIdx.x;
    const int bn   = blockIdx.x, bm = blockIdx.y;
    const int wid  = tid >> 5, lane = tid & 31;
    const int wm   = wid & 3;      // 4 warps along M (32 rows each)
    const int wn   = wid >> 2;     // 2 warps along N (64 cols each)

    uint32_t sbase = smem_u32(dynsmem);
    const uint32_t Abuf[2] = { sbase,             sbase + TBUF };
    const uint32_t Bbuf[2] = { sbase + 2 * TBUF,  sbase + 3 * TBUF };

    if (tid < 128) wsq_s[tid] = g_wsq[bn * 128 + tid];

    const int r = tid >> 3;        // 0..31 (row base, +32*i)
    const int c = tid & 7;         // 16B chunk within 128B row

    // async-load one BK=64 slice (kt) of A and B into buffer `bf`
    auto issue = [&](int kt, int bf) {
        #pragma unroll
        for (int i = 0; i < 4; ++i) {
            int row = r + 32 * i;
            cp16(Abuf[bf] + row * PITCH + c * 16,
                 (const char*)(g_Xb + (size_t)(bm * 128 + row) * D_ + kt * 64) + c * 16);
            cp16(Bbuf[bf] + row * PITCH + c * 16,
                 (const char*)(g_Wt + (size_t)(bn * 128 + row) * D_ + kt * 64) + c * 16);
        }
    };

    issue(0, 0); CP_COMMIT();
    issue(1, 1); CP_COMMIT();

    float acc[2][8][4];
    #pragma unroll
    for (int mt = 0; mt < 2; ++mt)
        #pragma unroll
        for (int nt = 0; nt < 8; ++nt)
            #pragma unroll
            for (int q = 0; q < 4; ++q) acc[mt][nt][q] = 0.f;

    #pragma unroll 1
    for (int kt = 0; kt < 8; ++kt) {
        if (kt < 7) CP_WAIT1(); else CP_WAIT0();
        __syncthreads();
        const uint32_t Ab = Abuf[kt & 1], Bb = Bbuf[kt & 1];

        #pragma unroll
        for (int ks = 0; ks < 4; ++ks) {
            uint32_t a[2][4];
            #pragma unroll
            for (int mt = 0; mt < 2; ++mt) {
                uint32_t addr = Ab + (uint32_t)((wm * 32 + mt * 16 + (lane & 15)) * PITCH
                                                + (ks * 16 + (lane >> 4) * 8) * 2);
                ldm_x4(a[mt][0], a[mt][1], a[mt][2], a[mt][3], addr);
            }
            uint32_t b[8][2];
            #pragma unroll
            for (int np = 0; np < 4; ++np) {
                // B stored [n][k] (k-contiguous) == same as A -> NON-trans ldmatrix.
                // lanes 0-7: n0-7/k0-7 (b0 of n-low), 8-15: n0-7/k8-15 (b1 of n-low),
                // 16-23: n8-15/k0-7, 24-31: n8-15/k8-15.
                uint32_t nrow = wn * 64 + np * 16 + (lane & 7) + ((lane >> 4) << 3);
                uint32_t koff = ks * 16 + (((lane >> 3) & 1) << 3);
                uint32_t addr = Bb + nrow * PITCH + koff * 2;
                ldm_x4(b[2 * np][0], b[2 * np][1], b[2 * np + 1][0], b[2 * np + 1][1], addr);
            }
            #pragma unroll
            for (int mt = 0; mt < 2; ++mt)
                #pragma unroll
                for (int nt = 0; nt < 8; ++nt)
                    mma16816(acc[mt][nt], a[mt], b[nt]);
        }
        __syncthreads();
        if (kt + 2 < 8) { issue(kt + 2, kt & 1); CP_COMMIT(); }
    }

    // epilogue: v = (xsq - 2*dot) + wsq  ->  fp16
    const int g = lane >> 2, th2 = (lane & 3) * 2;
    #pragma unroll
    for (int mt = 0; mt < 2; ++mt) {
        int row0 = bm * 128 + wm * 32 + mt * 16 + g;
        float xs0 = g_xsq[row0], xs1 = g_xsq[row0 + 8];
        __half* d0 = g_d2h + (size_t)row0 * K_ + bn * 128 + wn * 64;
        __half* d1 = d0 + (size_t)8 * K_;
        #pragma unroll
        for (int nt = 0; nt < 8; ++nt) {
            int col = wn * 64 + nt * 8 + th2;
            float w0 = wsq_s[col], w1 = wsq_s[col + 1];
            float v00 = (xs0 - 2.0f * acc[mt][nt][0]) + w0;
            float v01 = (xs0 - 2.0f * acc[mt][nt][1]) + w1;
            float v10 = (xs1 - 2.0f * acc[mt][nt][2]) + w0;
            float v11 = (xs1 - 2.0f * acc[mt][nt][3]) + w1;
            __half2 h0 = __floats2half2_rn(v00, v01);
            __half2 h1 = __floats2half2_rn(v10, v11);
            *(__half2*)(d0 + nt * 8 + th2) = h0;
            *(__half2*)(d1 + nt * 8 + th2) = h1;
        }
    }
}

// ---------------- argmin scan + exact fp32 rescore of near-ties ----------------
__global__ void k_argmin(const float* __restrict__ X, float* __restrict__ out_am) {
    __shared__ int s_cnt[8];
    __shared__ int s_list[8][64];
    int wid = threadIdx.x >> 5, lane = threadIdx.x & 31;
    int row = blockIdx.x * 8 + wid;

    const uint4* p = (const uint4*)(g_d2h + (size_t)row * K_);
    float vals[32];                 // vals[i*8+s] -> k = i*256 + lane*8 + s
    #pragma unroll
    for (int i = 0; i < 4; ++i) {
        uint4 v = p[i * 32 + lane];
        uint32_t u[4] = {v.x, v.y, v.z, v.w};
        #pragma unroll
        for (int q = 0; q < 4; ++q) {
            float2 f = __half22float2(*(__half2*)&u[q]);
            vals[i * 8 + q * 2 + 0] = fmaxf(f.x, 0.f);
            vals[i * 8 + q * 2 + 1] = fmaxf(f.y, 0.f);
        }
    }
    unsigned long long best = ~0ull;
    #pragma unroll
    for (int i = 0; i < 4; ++i)
        #pragma unroll
        for (int s = 0; s < 8; ++s) {
            int k = i * 256 + lane * 8 + s;
            unsigned long long pk =
                ((unsigned long long)__float_as_uint(vals[i * 8 + s]) << 32) | (unsigned)k;
            best = min(best, pk);
        }
    #pragma unroll
    for (int o = 16; o; o >>= 1) {
        unsigned long long other = __shfl_xor_sync(0xFFFFFFFFu, best, o);
        best = min(best, other);
    }
    float thr = __uint_as_float((unsigned)(best >> 32)) + TAU;
    int cct = 0;
    #pragma unroll
    for (int t = 0; t < 32; ++t) cct += (vals[t] <= thr);
    #pragma unroll
    for (int o = 16; o; o >>= 1) cct += __shfl_xor_sync(0xFFFFFFFFu, cct, o);

    int kfin;
    if (cct == 1) {
        kfin = (int)(best & 0xFFFFFFFFull);      // unique candidate == exact argmin
    } else {
        if (lane == 0) s_cnt[wid] = 0;
        __syncwarp();
        #pragma unroll
        for (int i = 0; i < 4; ++i)
            #pragma unroll
            for (int s = 0; s < 8; ++s)
                if (vals[i * 8 + s] <= thr) {
                    int pos = atomicAdd(&s_cnt[wid], 1);
                    if (pos < 64) s_list[wid][pos] = i * 256 + lane * 8 + s;
                }
        __syncwarp();
        int n = min(s_cnt[wid], 64);
        float xs = g_xsq[row];
        const float* xr = X + (size_t)row * D_;
        unsigned long long eb = ~0ull;
        for (int cc = 0; cc < n; ++cc) {
            int k = s_list[wid][cc];
            const float* wr = g_Wtf + (size_t)k * D_;
            float s = 0.f;
            #pragma unroll
            for (int j = 0; j < 16; ++j)
                s += xr[lane + j * 32] * wr[lane + j * 32];
            #pragma unroll
            for (int o = 16; o; o >>= 1) s += __shfl_xor_sync(0xFFFFFFFFu, s, o);
            float d2 = (xs - 2.0f * s) + g_wsq[k];
            float d  = __fsqrt_rn(fmaxf(d2, 0.0f));
            unsigned long long pk = ((unsigned long long)__float_as_uint(d) << 32) | (unsigned)k;
            eb = min(eb, pk);
        }
        kfin = (int)(eb & 0xFFFFFFFFull);
    }
    if (lane == 0) {
        g_assign[row] = kfin;
        out_am[row] = (float)kfin;
    }
}

// ---------------- counts + class histogram ----------------
__global__ void k_post(const int* __restrict__ keys) {
    int b = blockIdx.x * blockDim.x + threadIdx.x;
    if (b >= B_) return;
    int k = g_assign[b];
    atomicAdd(&g_counts[k], 1);
    atomicAdd(&g_bhist[k * C_ + keys[b]], 1);
}

// ---------------- cluster-size EMA, normalization, prefix scan ----------------
__global__ void k_stats(const float* __restrict__ cluster_size, float* __restrict__ out_ncs) {
    __shared__ float red[K_];
    __shared__ int   scan[K_];
    int t = threadIdx.x;
    int cnt = g_counts[t];
    float nidx = (cnt == 0) ? 1.0f : (float)cnt;
    float ncs = cluster_size[t] * GAM() + OMG() * nidx;
    out_ncs[t] = ncs;

    red[t] = ncs; __syncthreads();
    #pragma unroll
    for (int o = 512; o; o >>= 1) { if (t < o) red[t] += red[t + o]; __syncthreads(); }
    float n = red[0];
    g_csnorm[t] = ((ncs + 1e-5f) / (n + KEPS())) * n;

    scan[t] = cnt; __syncthreads();
    for (int o = 1; o < K_; o <<= 1) {
        int v = (t >= o) ? scan[t - o] : 0;
        __syncthreads();
        scan[t] += v;
        __syncthreads();
    }
    int excl = scan[t] - cnt;
    g_offsets[t] = excl;
    g_cursor[t]  = excl;
}

// ---------------- counting-sort scatter ----------------
__global__ void k_scatter() {
    int b = blockIdx.x * blockDim.x + threadIdx.x;
    if (b >= B_) return;
    int k = g_assign[b];
    int pos = atomicAdd(&g_cursor[k], 1);
    g_order[pos] = b;
}

// ---------------- per-cluster embed_sum (coalesced gather, MLP=4) ----------------
__global__ void k_embed(const float* __restrict__ X) {
    int k = blockIdx.x;
    int d = threadIdx.x;
    int start = g_offsets[k], cnt = g_counts[k];
    const int* ord = g_order + start;
    float a0 = 0.f, a1 = 0.f, a2 = 0.f, a3 = 0.f;
    int i = 0;
    for (; i + 4 <= cnt; i += 4) {
        int b0 = ord[i + 0], b1 = ord[i + 1], b2 = ord[i + 2], b3 = ord[i + 3];
        a0 += X[(size_t)b0 * D_ + d];
        a1 += X[(size_t)b1 * D_ + d];
        a2 += X[(size_t)b2 * D_ + d];
        a3 += X[(size_t)b3 * D_ + d];
    }
    for (; i < cnt; ++i) a0 += X[(size_t)ord[i] * D_ + d];
    g_es[(size_t)k * D_ + d] = (a0 + a1) + (a2 + a3);
}

// ---------------- embed_avg EMA + weight ----------------
__global__ void k_ema(const float* __restrict__ ea,
                      float* __restrict__ out_w, float* __restrict__ out_nea) {
    __shared__ float tile[32][33];
    int d0 = blockIdx.x * 32, k0 = blockIdx.y * 32;
    int tx = threadIdx.x, ty = threadIdx.y;
    tile[ty][tx] = g_es[(size_t)(k0 + ty) * D_ + d0 + tx];
    __syncthreads();
    int d = d0 + ty, k = k0 + tx;
    size_t idx = (size_t)d * K_ + k;
    float nea = ea[idx] * GAM() + OMG() * tile[tx][ty];
    out_nea[idx] = nea;
    out_w[idx]   = nea / g_csnorm[k];
}

// ---------------- hist EMA ----------------
__global__ void k_hist(const float* __restrict__ hist, float* __restrict__ out_h) {
    int i = blockIdx.x * blockDim.x + threadIdx.x;
    if (i < K_ * C_) out_h[i] = hist[i] * GAM() + OMG() * (float)g_bhist[i];
}

// ---------------- launch ----------------
extern "C" void kernel_launch(void* const* d_in, const int* in_sizes, int n_in,
                              void* d_out, int out_size) {
    const float* X    = (const float*)d_in[0];
    const int*   keys = (const int*)  d_in[1];
    const float* W    = (const float*)d_in[2];
    const float* cs   = (const float*)d_in[3];
    const float* ea   = (const float*)d_in[4];
    const float* hist = (const float*)d_in[5];

    float* out      = (float*)d_out;
    float* out_w    = out;
    float* out_ncs  = out + 524288;
    float* out_nea  = out + 525312;
    float* out_hist = out + 1049600;
    float* out_am   = out + 1152000;

    cudaFuncSetAttribute(k_gemm_bf16, cudaFuncAttributeMaxDynamicSharedMemorySize, 4 * TBUF);

    k_init<<<(K_ * C_ + 255) / 256, 256>>>();
    k_xconv<<<(B_ * 32) / 256, 256>>>(X);
    k_wt<<<dim3(D_ / 32, K_ / 32), dim3(32, 32)>>>(W);
    k_wsq<<<K_, 128>>>(W);

    k_gemm_bf16<<<dim3(K_ / 128, B_ / 128), 256, 4 * TBUF>>>();

    k_argmin<<<B_ / 8, 256>>>(X, out_am);
    k_post<<<B_ / 256, 256>>>(keys);
    k_stats<<<1, K_>>>(cs, out_ncs);
    k_scatter<<<B_ / 256, 256>>>();
    k_embed<<<K_, D_>>>(X);
    k_ema<<<dim3(D_ / 32, K_ / 32), dim3(32, 32)>>>(ea, out_w, out_nea);
    k_hist<<<(K_ * C_ + 255) / 256, 256>>>(hist, out_hist);
}